// round 13
// baseline (speedup 1.0000x reference)
#include <cuda_runtime.h>
#include <cuda_bf16.h>

#define BB 4
#define CC 64
#define HH 128
#define WW 128
#define HWSZ 16384
#define HO 256
#define WO 256
#define ECP 128          // padded channel-last stride for g_enc2

typedef unsigned long long u64;
typedef unsigned int u32;

// ---------------- scratch (static device arrays: allocation-free) ----------
// compressed features, NHWC bf16 hi/lo: ((b*HWSZ + pixel)*64 + ch)
__device__ __nv_bfloat16 g_chi[BB*HWSZ*64];
__device__ __nv_bfloat16 g_clo[BB*HWSZ*64];
// encode weights: 18 units (tap,half) of [128 oc x 128B rows: hi32ic|lo32ic],
// PRE-SWIZZLED (SW128), scaled by BN inv
__device__ __nv_bfloat16 g_w[18*128*64];
__device__ float g_shift[128];
// encoded logits, channel-last: [b][Y][x][128]
__device__ float g_enc2[BB*HH*WW*ECP];

// ---- packed f32x2 helpers ----
__device__ __forceinline__ u64 pk2(float lo, float hi) {
    u64 r; asm("mov.b64 %0, {%1, %2};" : "=l"(r) : "f"(lo), "f"(hi)); return r;
}
__device__ __forceinline__ u64 fma2(u64 a, u64 b, u64 c) {
    u64 d; asm("fma.rn.f32x2 %0, %1, %2, %3;" : "=l"(d) : "l"(a), "l"(b), "l"(c)); return d;
}
__device__ __forceinline__ float2 up2(u64 v) {
    float2 f; asm("mov.b64 {%0, %1}, %2;" : "=f"(f.x), "=f"(f.y) : "l"(v)); return f;
}
__device__ __forceinline__ u32 smem_u32(const void* p) {
    u32 a; asm("{ .reg .u64 t; cvta.to.shared.u64 t, %1; cvt.u32.u64 %0, t; }" : "=r"(a) : "l"(p));
    return a;
}
__device__ __forceinline__ u32 pack_bf2(float a, float b) {
    __nv_bfloat162 t = __floats2bfloat162_rn(a, b);
    return *reinterpret_cast<u32*>(&t);
}

#define SW128(off) ((off) ^ (((off) >> 3) & 0x70))

// ---- Ampere-style async copy + ldmatrix + mma.sync ----
__device__ __forceinline__ void cpa16(u32 dst, const void* src, bool ok) {
    int sz = ok ? 16 : 0;
    asm volatile("cp.async.cg.shared.global [%0], [%1], 16, %2;"
                 :: "r"(dst), "l"(src), "r"(sz) : "memory");
}
__device__ __forceinline__ void cpa_commit() {
    asm volatile("cp.async.commit_group;" ::: "memory");
}
template<int N>
__device__ __forceinline__ void cpa_wait() {
    asm volatile("cp.async.wait_group %0;" :: "n"(N) : "memory");
}
__device__ __forceinline__ void ldsm_x4(u32* r, u32 addr) {
    asm volatile("ldmatrix.sync.aligned.m8n8.x4.shared.b16 {%0,%1,%2,%3}, [%4];"
                 : "=r"(r[0]), "=r"(r[1]), "=r"(r[2]), "=r"(r[3]) : "r"(addr));
}
__device__ __forceinline__ void mma16816(float* c, const u32* a, const u32* b) {
    asm volatile(
        "mma.sync.aligned.m16n8k16.row.col.f32.bf16.bf16.f32 "
        "{%0,%1,%2,%3}, {%4,%5,%6,%7}, {%8,%9}, {%0,%1,%2,%3};"
        : "+f"(c[0]), "+f"(c[1]), "+f"(c[2]), "+f"(c[3])
        : "r"(a[0]), "r"(a[1]), "r"(a[2]), "r"(a[3]), "r"(b[0]), "r"(b[1]));
}

// ============================================================================
// Kernel 0: prep — split/scale encode weights; pack hi|lo of 32 ic into one
// 128B row per oc, per (tap, ic-half) unit; SW128 pre-swizzle; BN shifts.
// ============================================================================
__global__ __launch_bounds__(256) void prep_kernel(
    const float* __restrict__ Wenc, const float* __restrict__ encb,
    const float* __restrict__ gamma, const float* __restrict__ beta,
    const float* __restrict__ mean,  const float* __restrict__ var)
{
    int t = blockIdx.x*256 + threadIdx.x;
    if (t < 128) {
        if (t < 100) {
            float inv = gamma[t] * rsqrtf(var[t] + 1e-5f);
            g_shift[t] = beta[t] - mean[t]*inv + encb[t]*inv;
        } else g_shift[t] = 0.f;
    }
    if (t >= 9*128*64) return;
    int tap = t >> 13;
    int rem = t & 8191;
    int oc  = rem >> 6;
    int ic  = rem & 63;
    float w = 0.f;
    if (oc < 100) {
        float inv = gamma[oc] * rsqrtf(var[oc] + 1e-5f);
        w = Wenc[(oc*64 + ic)*9 + tap] * inv;
    }
    __nv_bfloat16 h = __float2bfloat16(w);
    __nv_bfloat16 l = __float2bfloat16(w - __bfloat162float(h));
    int hu  = ic >> 5;          // ic half -> unit
    int icl = ic & 31;
    int unit = tap*2 + hu;
    u32 swh = SW128((u32)(oc*128 + icl*2));
    u32 swl = SW128((u32)(oc*128 + 64 + icl*2));
    g_w[unit*8192 + (swh >> 1)] = h;
    g_w[unit*8192 + (swl >> 1)] = l;
}

// ============================================================================
// Kernel 1: compress = 1x1 conv (64->64) + BN + ReLU -> NHWC bf16 hi/lo
// ============================================================================
__global__ __launch_bounds__(256) void compress_kernel(
    const float* __restrict__ X, const float* __restrict__ Wc,
    const float* __restrict__ gamma, const float* __restrict__ beta,
    const float* __restrict__ mean,  const float* __restrict__ var)
{
    __shared__ __align__(16) float ws[64*16];   // [ic][oc]
    __shared__ float sc[16], bs[16];
    int tid = threadIdx.x;
    int q   = blockIdx.y;           // oc quarter

    for (int t = tid; t < 1024; t += 256) {
        int oc = t >> 6, ic = t & 63;
        ws[ic*16 + oc] = Wc[(q*16 + oc)*64 + ic];
    }
    if (tid < 16) {
        int oc = q*16 + tid;
        float inv = gamma[oc] * rsqrtf(var[oc] + 1e-5f);
        sc[tid] = inv;
        bs[tid] = beta[oc] - mean[oc]*inv;
    }
    __syncthreads();

    int b = blockIdx.z;
    int p = ((blockIdx.x << 8) + tid) << 1;       // even pixel index
    const float2* Xb = reinterpret_cast<const float2*>(X + b*CC*HWSZ + p);

    u64 acc0[8], acc1[8];
#pragma unroll
    for (int i = 0; i < 8; i++) { acc0[i] = 0ULL; acc1[i] = 0ULL; }

    for (int ic0 = 0; ic0 < 64; ic0 += 8) {
        float2 xv[8];
#pragma unroll
        for (int u = 0; u < 8; u++) xv[u] = Xb[(ic0 + u)*(HWSZ/2)];
#pragma unroll
        for (int u = 0; u < 8; u++) {
            int ic = ic0 + u;
            u64 xa = pk2(xv[u].x, xv[u].x);
            u64 xc = pk2(xv[u].y, xv[u].y);
            const ulonglong2* w2 = reinterpret_cast<const ulonglong2*>(ws + (ic << 4));
#pragma unroll
            for (int m = 0; m < 4; m++) {
                ulonglong2 w = w2[m];
                acc0[2*m]   = fma2(xa, w.x, acc0[2*m]);
                acc0[2*m+1] = fma2(xa, w.y, acc0[2*m+1]);
                acc1[2*m]   = fma2(xc, w.x, acc1[2*m]);
                acc1[2*m+1] = fma2(xc, w.y, acc1[2*m+1]);
            }
        }
    }

    u32 uh[16], ul[16];
#pragma unroll
    for (int k = 0; k < 8; k++) {
        float2 f0 = up2(acc0[k]);
        float2 f1 = up2(acc1[k]);
        int oc = 2*k;
        float v00 = fmaxf(f0.x*sc[oc]   + bs[oc],   0.f);
        float v01 = fmaxf(f0.y*sc[oc+1] + bs[oc+1], 0.f);
        float v10 = fmaxf(f1.x*sc[oc]   + bs[oc],   0.f);
        float v11 = fmaxf(f1.y*sc[oc+1] + bs[oc+1], 0.f);
        float h00 = __bfloat162float(__float2bfloat16(v00));
        float h01 = __bfloat162float(__float2bfloat16(v01));
        float h10 = __bfloat162float(__float2bfloat16(v10));
        float h11 = __bfloat162float(__float2bfloat16(v11));
        uh[k]   = pack_bf2(v00, v01);
        ul[k]   = pack_bf2(v00 - h00, v01 - h01);
        uh[8+k] = pack_bf2(v10, v11);
        ul[8+k] = pack_bf2(v10 - h10, v11 - h11);
    }
    size_t base = ((size_t)b*HWSZ + p)*64 + q*16;
    const uint4* sh_ = reinterpret_cast<const uint4*>(uh);
    const uint4* sl_ = reinterpret_cast<const uint4*>(ul);
    *reinterpret_cast<uint4*>(g_chi + base)      = sh_[0];
    *reinterpret_cast<uint4*>(g_chi + base + 8)  = sh_[1];
    *reinterpret_cast<uint4*>(g_chi + base + 64) = sh_[2];
    *reinterpret_cast<uint4*>(g_chi + base + 72) = sh_[3];
    *reinterpret_cast<uint4*>(g_clo + base)      = sl_[0];
    *reinterpret_cast<uint4*>(g_clo + base + 8)  = sl_[1];
    *reinterpret_cast<uint4*>(g_clo + base + 64) = sl_[2];
    *reinterpret_cast<uint4*>(g_clo + base + 72) = sl_[3];
}

// ============================================================================
// Kernel 2: encode as mma.sync GEMM. 18 half-tap units (32 ic, hi|lo packed
// in one 128B row), 32KB/unit, 64KB double buffer -> 2 blocks/SM.
// ============================================================================
#define EBUF 32768
#define ESM_TOTAL 68608   // 1024 hdr + max(2*32KB staging, 128*132*4 epilogue)

__global__ __launch_bounds__(256, 2) void encode_mma_kernel()
{
    extern __shared__ char dsm[];
    u32 sb = (smem_u32(dsm) + 1023) & ~1023u;
    int tid  = threadIdx.x;
    int wid  = tid >> 5, lane = tid & 31;
    int warpM = wid & 3;          // oc:  warpM*32
    int warpN = wid >> 2;         // px:  warpN*64
    int Y = blockIdx.x;
    int b = blockIdx.y;

    // stage one (tap, half) unit: A 16KB pre-swizzled copy + B 16KB gather
    auto stage = [&](int u, u32 bufb) {
        int tap = u >> 1, h = u & 1;
        const uint4* sA = reinterpret_cast<const uint4*>(g_w + u*8192);
#pragma unroll
        for (int k = 0; k < 4; k++) {
            int i = tid + k*256;                  // 0..1023
            cpa16(bufb + i*16, sA + i, true);
        }
        int dy = tap / 3, dx = tap - dy*3;
        int ysrc = Y + dy - 1;
        bool yok = (unsigned)ysrc < 128u;
#pragma unroll
        for (int k = 0; k < 4; k++) {
            int i = tid + k*256;                  // 0..1023
            int px   = i >> 3;
            int sub  = i & 7;
            int hilo = sub >> 2;
            int segl = sub & 3;
            int xsrc = px + dx - 1;
            bool ok = yok && ((unsigned)xsrc < 128u);
            const __nv_bfloat16* srcb = hilo ? g_clo : g_chi;
            size_t so = ok ? (((size_t)b*HWSZ + ysrc*128 + xsrc)*64 + h*32 + segl*8) : 0;
            u32 dsto = SW128((u32)(px*128 + hilo*64 + segl*16));
            cpa16(bufb + 16384 + dsto, srcb + so, ok);
        }
        cpa_commit();
    };

    float c[2][8][4];
#pragma unroll
    for (int t = 0; t < 2; t++)
#pragma unroll
        for (int f = 0; f < 8; f++)
#pragma unroll
            for (int i = 0; i < 4; i++) c[t][f][i] = 0.f;

    int rowA  = (lane & 15);
    int colA  = (lane >> 4) * 16;
    int rowB  = (lane & 7) + ((lane >> 4) & 1) * 8;
    int colB  = ((lane >> 3) & 1) * 16;

    stage(0, sb);

    for (int u = 0; u < 18; u++) {
        u32 bufb = sb + (u & 1)*EBUF;
        if (u < 17) { stage(u + 1, sb + ((u + 1) & 1)*EBUF); cpa_wait<1>(); }
        else        { cpa_wait<0>(); }
        __syncthreads();

#pragma unroll
        for (int ks = 0; ks < 2; ks++) {
            u32 ah[2][4], al[2][4];
#pragma unroll
            for (int t = 0; t < 2; t++) {
                u32 rb = (u32)((warpM*32 + t*16 + rowA)*128);
                ldsm_x4(ah[t], bufb + SW128(rb + ks*32 + colA));          // hi: bytes 0-63
                ldsm_x4(al[t], bufb + SW128(rb + 64 + ks*32 + colA));     // lo: bytes 64-127
            }
            u32 bh[8][2], bl[8][2];
#pragma unroll
            for (int fp = 0; fp < 4; fp++) {
                u32 rb = (u32)((warpN*64 + fp*16 + rowB)*128);
                u32 r[4];
                ldsm_x4(r, bufb + 16384 + SW128(rb + ks*32 + colB));
                bh[2*fp][0] = r[0]; bh[2*fp][1] = r[1];
                bh[2*fp+1][0] = r[2]; bh[2*fp+1][1] = r[3];
                ldsm_x4(r, bufb + 16384 + SW128(rb + 64 + ks*32 + colB));
                bl[2*fp][0] = r[0]; bl[2*fp][1] = r[1];
                bl[2*fp+1][0] = r[2]; bl[2*fp+1][1] = r[3];
            }
#pragma unroll
            for (int t = 0; t < 2; t++)
#pragma unroll
                for (int f = 0; f < 8; f++) {
                    mma16816(c[t][f], ah[t], bh[f]);
                    mma16816(c[t][f], ah[t], bl[f]);
                    mma16816(c[t][f], al[t], bh[f]);
                }
        }
        __syncthreads();
    }

    // ---- epilogue: transpose via smem, coalesced channel-last store ----
    float* strans = reinterpret_cast<float*>((char*)dsm + (sb - smem_u32(dsm)));
#pragma unroll
    for (int t = 0; t < 2; t++) {
        int row = warpM*32 + t*16 + (lane >> 2);
#pragma unroll
        for (int f = 0; f < 8; f++) {
            int col = warpN*64 + f*8 + (lane & 3)*2;
            strans[col*132 + row]         = c[t][f][0];
            strans[(col+1)*132 + row]     = c[t][f][1];
            strans[col*132 + row + 8]     = c[t][f][2];
            strans[(col+1)*132 + row + 8] = c[t][f][3];
        }
    }
    __syncthreads();

    float* ob = g_enc2 + ((size_t)b*HWSZ + Y*128)*ECP;
#pragma unroll
    for (int i = 0; i < 16; i++) {
        int idx = tid + i*256;          // 0..4095
        int px  = idx >> 5;
        int oc4 = idx & 31;
        float4 v  = *reinterpret_cast<const float4*>(strans + px*132 + oc4*4);
        float4 sh = *reinterpret_cast<const float4*>(g_shift + oc4*4);
        v.x += sh.x; v.y += sh.y; v.z += sh.z; v.w += sh.w;
        *reinterpret_cast<float4*>(ob + px*ECP + oc4*4) = v;
    }
}

// ============================================================================
// Kernel 3: CARAFE quad kernel. One thread = full 2x2 output quad (rows
// y0/y0+1, cols 2t/2t+1) which shares ALL 25 taps; 4 softmax weight sets.
// 128 threads/block over x-pairs; 25 LDS.128 per stage feed 16 outputs.
// Logit loads: one float4 per tap (subs 0-3 packed channel-last).
// ============================================================================
__global__ __launch_bounds__(128) void carafe_kernel(
    const float* __restrict__ X, float* __restrict__ out)
{
    __shared__ __align__(16) ulonglong2 stile[2][5*132];   // 21.1 KB
    int t = threadIdx.x;           // x-pair 0..127
    int Y = blockIdx.x;
    int b = blockIdx.y;
    int y0 = 2*Y;
    int x0 = 2*t;

    // 4 weight sets from packed float4 logits
    float w[4][25];
    {
        const float4* encp4 = reinterpret_cast<const float4*>(
            g_enc2 + ((size_t)b*HWSZ + Y*128 + t)*ECP);
        float mx0 = -1e30f, mx1 = -1e30f, mx2 = -1e30f, mx3 = -1e30f;
#pragma unroll
        for (int k = 0; k < 25; k++) {
            float4 v = encp4[k];
            w[0][k] = v.x; w[1][k] = v.y; w[2][k] = v.z; w[3][k] = v.w;
            mx0 = fmaxf(mx0, v.x); mx1 = fmaxf(mx1, v.y);
            mx2 = fmaxf(mx2, v.z); mx3 = fmaxf(mx3, v.w);
        }
        float s0 = 0.f, s1 = 0.f, s2 = 0.f, s3 = 0.f;
#pragma unroll
        for (int k = 0; k < 25; k++) {
            w[0][k] = __expf(w[0][k] - mx0); s0 += w[0][k];
            w[1][k] = __expf(w[1][k] - mx1); s1 += w[1][k];
            w[2][k] = __expf(w[2][k] - mx2); s2 += w[2][k];
            w[3][k] = __expf(w[3][k] - mx3); s3 += w[3][k];
        }
        s0 = 1.f/s0; s1 = 1.f/s1; s2 = 1.f/s2; s3 = 1.f/s3;
#pragma unroll
        for (int k = 0; k < 25; k++) {
            w[0][k] *= s0; w[1][k] *= s1; w[2][k] *= s2; w[3][k] *= s3;
        }
    }

    const float* Xb = X + b*CC*HWSZ;

    // fill geometry: rows Y-2..Y+2, cols -2..129 (stored +2), 660 entries
    int  foff[6];
    bool fval[6];
#pragma unroll
    for (int k = 0; k < 6; k++) {
        int idx = t + k*128;
        int i  = idx / 132;
        int cc = idx - i*132 - 2;
        int r  = Y - 2 + i;
        bool v = (idx < 660) && ((unsigned)r < 128u) && ((unsigned)cc < 128u);
        fval[k] = v;
        foff[k] = v ? r*128 + cc : 0;
    }

    // prologue: channels 0..3 into buffer 0
    float rv[6][4];
#pragma unroll
    for (int k = 0; k < 6; k++) {
        const float* p = Xb + foff[k];
#pragma unroll
        for (int j = 0; j < 4; j++) rv[k][j] = fval[k] ? p[j*HWSZ] : 0.f;
    }
#pragma unroll
    for (int k = 0; k < 6; k++)
        if (t + k*128 < 660) {
            ulonglong2 pk;
            pk.x = pk2(rv[k][0], rv[k][1]);
            pk.y = pk2(rv[k][2], rv[k][3]);
            stile[0][t + k*128] = pk;
        }
    __syncthreads();

    float* ob00 = out + (size_t)b*CC*(HO*WO) + y0*WO + x0;   // row y0
    float* ob10 = ob00 + WO;                                 // row y0+1

    for (int ci = 0; ci < 16; ci++) {
        int c = ci*4;
        // prefetch next 4 channels
        if (ci + 1 < 16) {
#pragma unroll
            for (int k = 0; k < 6; k++) {
                const float* p = Xb + (c+4)*HWSZ + foff[k];
#pragma unroll
                for (int j = 0; j < 4; j++) rv[k][j] = fval[k] ? p[j*HWSZ] : 0.f;
            }
        }

        const ulonglong2* tb = stile[ci & 1];
        u64 acc[4][2];
#pragma unroll
        for (int o = 0; o < 4; o++) { acc[o][0] = 0ULL; acc[o][1] = 0ULL; }
#pragma unroll
        for (int i = 0; i < 5; i++) {
            int base = i*132 + t;
#pragma unroll
            for (int j = 0; j < 5; j++) {
                int k = i*5 + j;
                ulonglong2 sv = tb[base + j];
#pragma unroll
                for (int o = 0; o < 4; o++) {
                    u64 ws = pk2(w[o][k], w[o][k]);
                    acc[o][0] = fma2(ws, sv.x, acc[o][0]);
                    acc[o][1] = fma2(ws, sv.y, acc[o][1]);
                }
            }
        }

        // stores: pair (x0, x0+1) -> float2, fully coalesced
#pragma unroll
        for (int p = 0; p < 2; p++) {
            float2 fL0 = up2(acc[0][p]);   // y0, x0 : ch c+2p, c+2p+1
            float2 fR0 = up2(acc[1][p]);   // y0, x1
            float2 fL1 = up2(acc[2][p]);   // y1, x0
            float2 fR1 = up2(acc[3][p]);   // y1, x1
            int cA = c + 2*p, cB = cA + 1;
            *reinterpret_cast<float2*>(ob00 + (size_t)cA*(HO*WO)) = make_float2(fL0.x, fR0.x);
            *reinterpret_cast<float2*>(ob00 + (size_t)cB*(HO*WO)) = make_float2(fL0.y, fR0.y);
            *reinterpret_cast<float2*>(ob10 + (size_t)cA*(HO*WO)) = make_float2(fL1.x, fR1.x);
            *reinterpret_cast<float2*>(ob10 + (size_t)cB*(HO*WO)) = make_float2(fL1.y, fR1.y);
        }

        if (ci + 1 < 16) {
            ulonglong2* buf = stile[(ci+1) & 1];
#pragma unroll
            for (int k = 0; k < 6; k++)
                if (t + k*128 < 660) {
                    ulonglong2 pk;
                    pk.x = pk2(rv[k][0], rv[k][1]);
                    pk.y = pk2(rv[k][2], rv[k][3]);
                    buf[t + k*128] = pk;
                }
        }
        __syncthreads();
    }
}

// ============================================================================
extern "C" void kernel_launch(void* const* d_in, const int* in_sizes, int n_in,
                              void* d_out, int out_size)
{
    const float* X          = (const float*)d_in[0];
    const float* comp_w     = (const float*)d_in[1];
    const float* comp_gamma = (const float*)d_in[2];
    const float* comp_beta  = (const float*)d_in[3];
    const float* comp_mean  = (const float*)d_in[4];
    const float* comp_var   = (const float*)d_in[5];
    const float* enc_w      = (const float*)d_in[6];
    const float* enc_b      = (const float*)d_in[7];
    const float* enc_gamma  = (const float*)d_in[8];
    const float* enc_beta   = (const float*)d_in[9];
    const float* enc_mean   = (const float*)d_in[10];
    const float* enc_var    = (const float*)d_in[11];
    float* out = (float*)d_out;

    cudaFuncSetAttribute(encode_mma_kernel,
                         cudaFuncAttributeMaxDynamicSharedMemorySize, ESM_TOTAL);

    prep_kernel<<<288, 256>>>(enc_w, enc_b, enc_gamma, enc_beta, enc_mean, enc_var);
    compress_kernel<<<dim3(32, 4, BB), 256>>>(X, comp_w, comp_gamma, comp_beta,
                                              comp_mean, comp_var);
    encode_mma_kernel<<<dim3(HH, BB), 256, ESM_TOTAL>>>();
    carafe_kernel<<<dim3(HH, BB), 128>>>(X, out);
}